// round 3
// baseline (speedup 1.0000x reference)
#include <cuda_runtime.h>
#include <cuda_bf16.h>
#include <math.h>
#include <stdint.h>

#define NROW 32768
#define DDIM 256
#define KCB  1024
#define NQ   4

// Output layout (concatenation of reference return tuple, all float32):
//   x_q          [NROW*DDIM]        at 0
//   mean_losses  [1]                at 8388608
//   all_indices  [NROW*NQ]          at 8388609
//   all_distances[NROW*NQ*KCB]      at 8519681   <-- ODD offset: scalar access only!
static const size_t OUT_LOSS = (size_t)NROW * DDIM;
static const size_t OUT_IDX  = OUT_LOSS + 1;
static const size_t OUT_DIST = OUT_IDX + (size_t)NROW * NQ;

// ---------------- scratch (static device globals; no allocation) ----------
__device__ __align__(16) float g_resid[(size_t)NROW * DDIM];   // 32 MB
__device__ __align__(16) float g_rn[NROW];
__device__ __align__(16) float g_cn[NQ * KCB];
__device__ __align__(16) int   g_idx[NROW];
__device__ int   g_minmax[2];
__device__ __align__(16) float g_Q0f[(size_t)NROW * KCB];      // 128 MB fp32 Q0
__device__ __align__(16) float g_SjM[21][KCB];                 // column sums per iteration
__device__ double g_loss[NQ];

// ---------------- init ---------------------------------------------------
__global__ void __launch_bounds__(256) k_init(const float* __restrict__ x,
                                              float* __restrict__ out) {
    int i = blockIdx.x * 256 + threadIdx.x;      // exactly NROW*DDIM threads
    g_resid[i] = x[i];
    out[i] = 0.0f;                               // x_q accumulator region
    if (i < NQ) g_loss[i] = 0.0;
    if (i < 21 * KCB) ((float*)g_SjM)[i] = 0.0f;
    if (i == 0) {
        g_minmax[0] = 0x7f800000;                // +inf
        g_minmax[1] = 0xff800000;                // -inf
    }
}

// ---------------- norms (warp per row) ------------------------------------
__device__ __forceinline__ float warp_sum(float s) {
#pragma unroll
    for (int o = 16; o > 0; o >>= 1) s += __shfl_xor_sync(0xffffffffu, s, o);
    return s;
}

__global__ void __launch_bounds__(256) k_cnorm(const float* __restrict__ cb) {
    int w = (blockIdx.x * blockDim.x + threadIdx.x) >> 5;  // 0..NQ*KCB-1
    int lane = threadIdx.x & 31;
    const float4* p = (const float4*)(cb + (size_t)w * DDIM);
    float4 a = p[lane], b = p[lane + 32];
    float s = a.x*a.x + a.y*a.y + a.z*a.z + a.w*a.w
            + b.x*b.x + b.y*b.y + b.z*b.z + b.w*b.w;
    s = warp_sum(s);
    if (!lane) g_cn[w] = s;
}

__global__ void __launch_bounds__(256) k_rownorm() {
    int w = (blockIdx.x * blockDim.x + threadIdx.x) >> 5;  // 0..NROW-1
    int lane = threadIdx.x & 31;
    const float4* p = (const float4*)(g_resid + (size_t)w * DDIM);
    float4 a = p[lane], b = p[lane + 32];
    float s = a.x*a.x + a.y*a.y + a.z*a.z + a.w*a.w
            + b.x*b.x + b.y*b.y + b.z*b.z + b.w*b.w;
    s = warp_sum(s);
    if (!lane) g_rn[w] = s;
}

// ---------------- distance GEMM (fp32 SIMT, 128x64 tile) ------------------
__global__ void __launch_bounds__(256) k_gemm(const float* __restrict__ B,
                                              float* __restrict__ dout, int q) {
    __shared__ float sA[16][132];   // [k][row], padded
    __shared__ float sB[16][68];    // [k][col], padded
    const int tid = threadIdx.x;
    const int bx = blockIdx.x;      // 0..15 (col tile of 64)
    const int by = blockIdx.y;      // 0..255 (row tile of 128)
    const int tx = tid & 15, ty = tid >> 4;
    const float* Ab = g_resid + (size_t)by * 128 * DDIM;
    const float* Bb = B + (size_t)bx * 64 * DDIM;

    float acc[8][4];
#pragma unroll
    for (int m = 0; m < 8; m++)
#pragma unroll
        for (int n = 0; n < 4; n++) acc[m][n] = 0.0f;

    for (int k0 = 0; k0 < DDIM; k0 += 16) {
#pragma unroll
        for (int h = 0; h < 2; h++) {
            int f = tid + h * 256;
            int r = f >> 2, cs = f & 3;
            float4 v = *(const float4*)(Ab + (size_t)r * DDIM + k0 + cs * 4);
            sA[cs*4+0][r] = v.x; sA[cs*4+1][r] = v.y;
            sA[cs*4+2][r] = v.z; sA[cs*4+3][r] = v.w;
        }
        {
            int r = tid >> 2, cs = tid & 3;
            float4 v = *(const float4*)(Bb + (size_t)r * DDIM + k0 + cs * 4);
            sB[cs*4+0][r] = v.x; sB[cs*4+1][r] = v.y;
            sB[cs*4+2][r] = v.z; sB[cs*4+3][r] = v.w;
        }
        __syncthreads();
#pragma unroll
        for (int kk = 0; kk < 16; kk++) {
            float4 a0 = *(const float4*)&sA[kk][ty * 8];
            float4 a1 = *(const float4*)&sA[kk][ty * 8 + 4];
            float4 bv = *(const float4*)&sB[kk][tx * 4];
            float av[8] = {a0.x,a0.y,a0.z,a0.w,a1.x,a1.y,a1.z,a1.w};
            float bb[4] = {bv.x,bv.y,bv.z,bv.w};
#pragma unroll
            for (int m = 0; m < 8; m++)
#pragma unroll
                for (int n = 0; n < 4; n++) acc[m][n] += av[m] * bb[n];
        }
        __syncthreads();
    }

    int colb = bx * 64 + tx * 4;
    float c0 = g_cn[q*KCB + colb + 0], c1 = g_cn[q*KCB + colb + 1];
    float c2 = g_cn[q*KCB + colb + 2], c3 = g_cn[q*KCB + colb + 3];
#pragma unroll
    for (int m = 0; m < 8; m++) {
        int row = by * 128 + ty * 8 + m;
        float rv = g_rn[row];
        // dout region is only 4-byte aligned (odd base offset) -> scalar stores
        float* o = dout + (((size_t)(row * NQ + q)) << 10) + colb;
        o[0] = rv + c0 - 2.0f * acc[m][0];
        o[1] = rv + c1 - 2.0f * acc[m][1];
        o[2] = rv + c2 - 2.0f * acc[m][2];
        o[3] = rv + c3 - 2.0f * acc[m][3];
    }
}

// ---------------- stage 0: row argmin (first-min tie-break) ----------------
__global__ void __launch_bounds__(256) k_argmin(const float* __restrict__ dout) {
    int w = (blockIdx.x * blockDim.x + threadIdx.x) >> 5;  // row
    int lane = threadIdx.x & 31;
    const float* dr = dout + (((size_t)(w * NQ)) << 10);
    float best = __int_as_float(0x7f800000);
    int bi = 0;
#pragma unroll 4
    for (int c = 0; c < 32; c++) {
        int j = c * 32 + lane;
        float v = dr[j];
        if (v < best) { best = v; bi = j; }
    }
#pragma unroll
    for (int o = 16; o > 0; o >>= 1) {
        float ov = __shfl_xor_sync(0xffffffffu, best, o);
        int   oi = __shfl_xor_sync(0xffffffffu, bi, o);
        if (ov < best || (ov == best && oi < bi)) { best = ov; bi = oi; }
    }
    if (!lane) g_idx[w] = bi;
}

// ---------------- stage 3: global min/max over d --------------------------
__global__ void __launch_bounds__(256) k_minmax(const float* __restrict__ dout) {
    size_t stride = (size_t)gridDim.x * blockDim.x;
    float mn = __int_as_float(0x7f800000), mx = -mn;
    for (size_t e = blockIdx.x * (size_t)blockDim.x + threadIdx.x;
         e < (size_t)NROW * KCB; e += stride) {
        size_t i = e >> 10, j = e & 1023;
        float v = dout[((i * NQ + 3) << 10) + j];
        mn = fminf(mn, v); mx = fmaxf(mx, v);
    }
#pragma unroll
    for (int o = 16; o > 0; o >>= 1) {
        mn = fminf(mn, __shfl_xor_sync(0xffffffffu, mn, o));
        mx = fmaxf(mx, __shfl_xor_sync(0xffffffffu, mx, o));
    }
    __shared__ float smn[8], smx[8];
    int lane = threadIdx.x & 31, wp = threadIdx.x >> 5;
    if (!lane) { smn[wp] = mn; smx[wp] = mx; }
    __syncthreads();
    if (threadIdx.x == 0) {
        for (int i = 1; i < 8; i++) { mn = fminf(mn, smn[i]); mx = fmaxf(mx, smx[i]); }
        atomicMin(&g_minmax[0], __float_as_int(mn));   // all d >= 0 -> int order ok
        atomicMax(&g_minmax[1], __float_as_int(mx));
    }
}

// ---- stage 3: Q0 = exp(-dc/eps) fp32, + unscaled colsum -> g_SjM[1] ------
// Block = 64 rows; warp per row; lane owns columns c*32+lane.
__global__ void __launch_bounds__(256) k_expQ(const float* __restrict__ dout) {
    __shared__ float sacc[KCB];
    float mn = __int_as_float(g_minmax[0]);
    float mx = __int_as_float(g_minmax[1]);
    float middle = (mx + mn) * 0.5f;
    float ampl = mx - middle + 1e-5f;
    int tid = threadIdx.x;
    for (int j = tid; j < KCB; j += 256) sacc[j] = 0.0f;
    __syncthreads();
    int wp = tid >> 5, lane = tid & 31;
    float acc[32];
#pragma unroll
    for (int c = 0; c < 32; c++) acc[c] = 0.0f;
    for (int it = 0; it < 8; it++) {
        int row = blockIdx.x * 64 + it * 8 + wp;
        const float* dr = dout + (((size_t)(row * NQ + 3)) << 10);
        float* qrow = g_Q0f + ((size_t)row << 10);
#pragma unroll
        for (int c = 0; c < 32; c++) {
            int j = c * 32 + lane;
            float dc = (dr[j] - middle) / ampl;
            float qv = expf(-dc / 0.1f);
            qrow[j] = qv;
            acc[c] += qv;
        }
    }
#pragma unroll
    for (int c = 0; c < 32; c++) atomicAdd(&sacc[c * 32 + lane], acc[c]);
    __syncthreads();
    for (int j = tid; j < KCB; j += 256) atomicAdd(&g_SjM[1][j], sacc[j]);
}

// ---- fused Sinkhorn pass t (1..19): b=1/(K*S[t]); s_i=Q0·b; a_i=1/(N*s_i);
//      S[t+1] += a_i * Q0_i.   One Q0 read per pass (row held in registers).
__global__ void __launch_bounds__(256) k_iter(int t) {
    __shared__ float sb[KCB];
    __shared__ float sacc[KCB];
    int tid = threadIdx.x;
    const float* St = g_SjM[t];
    for (int j = tid; j < KCB; j += 256) {
        sb[j] = 1.0f / (1024.0f * St[j]);
        sacc[j] = 0.0f;
    }
    __syncthreads();
    int wp = tid >> 5, lane = tid & 31;
    float acc[32];
#pragma unroll
    for (int c = 0; c < 32; c++) acc[c] = 0.0f;
    for (int it = 0; it < 8; it++) {
        int row = blockIdx.x * 64 + it * 8 + wp;
        const float* qrow = g_Q0f + ((size_t)row << 10);
        float q[32];
        float s = 0.0f;
#pragma unroll
        for (int c = 0; c < 32; c++) {
            int j = c * 32 + lane;
            q[c] = qrow[j];
            s += q[c] * sb[j];
        }
        s = warp_sum(s);
        float a = 1.0f / (32768.0f * s);
#pragma unroll
        for (int c = 0; c < 32; c++) acc[c] += a * q[c];
    }
#pragma unroll
    for (int c = 0; c < 32; c++) atomicAdd(&sacc[c * 32 + lane], acc[c]);
    __syncthreads();
    for (int j = tid; j < KCB; j += 256) atomicAdd(&g_SjM[t + 1][j], sacc[j]);
}

// ---- stage 3 final: literal argmax_j Q0_ij * b20_j (first-max tie-break) --
__global__ void __launch_bounds__(256) k_fidx() {
    __shared__ float sb[KCB];
    int tid = threadIdx.x;
    for (int j = tid; j < KCB; j += 256)
        sb[j] = 1.0f / (1024.0f * g_SjM[20][j]);
    __syncthreads();
    int wp = tid >> 5, lane = tid & 31;
    int row = blockIdx.x * 8 + wp;
    const float* qrow = g_Q0f + ((size_t)row << 10);
    float best = -1.0f;   // Q values are > 0
    int bi = 0;
#pragma unroll 4
    for (int c = 0; c < 32; c++) {
        int j = c * 32 + lane;
        float v = qrow[j] * sb[j];
        if (v > best) { best = v; bi = j; }
    }
#pragma unroll
    for (int o = 16; o > 0; o >>= 1) {
        float ov = __shfl_xor_sync(0xffffffffu, best, o);
        int   oi = __shfl_xor_sync(0xffffffffu, bi, o);
        if (ov > best || (ov == best && oi < bi)) { best = ov; bi = oi; }
    }
    if (!lane) g_idx[row] = bi;
}

// ---------------- residual/x_q update, loss, index write ------------------
__global__ void __launch_bounds__(256) k_update(const float* __restrict__ cb,
                                                float* __restrict__ out,
                                                int q, int forceZero) {
    int row = (blockIdx.x * blockDim.x + threadIdx.x) >> 5;
    int lane = threadIdx.x & 31;
    int idx = forceZero ? 0 : g_idx[row];
    const float4* c = (const float4*)(cb + ((size_t)(q * KCB + idx)) * DDIM);
    float4* r  = (float4*)(g_resid + (size_t)row * DDIM);
    float4* xq = (float4*)(out + (size_t)row * DDIM);
    float ls = 0;
#pragma unroll
    for (int h = 0; h < 2; h++) {
        int e = lane + h * 32;
        float4 cv = c[e], rv = r[e], xv = xq[e];
        float t0 = cv.x - rv.x, t1 = cv.y - rv.y, t2 = cv.z - rv.z, t3 = cv.w - rv.w;
        ls += t0*t0 + t1*t1 + t2*t2 + t3*t3;
        // x_res (value) == codeword; x_q += codeword; residual -= codeword
        xv.x += cv.x; xv.y += cv.y; xv.z += cv.z; xv.w += cv.w;
        rv.x -= cv.x; rv.y -= cv.y; rv.z -= cv.z; rv.w -= cv.w;
        r[e] = rv; xq[e] = xv;
    }
    ls = warp_sum(ls);
    if (!lane) {
        atomicAdd(&g_loss[q], (double)ls);
        out[OUT_IDX + (size_t)row * NQ + q] = (float)idx;
    }
}

__global__ void k_finalize(float* __restrict__ out) {
    double m = 0.0;
    for (int q = 0; q < NQ; q++)
        m += 1.25 * (g_loss[q] / (double)((size_t)NROW * DDIM));
    out[OUT_LOSS] = (float)(m / 4.0);
}

// ---------------- launcher ------------------------------------------------
extern "C" void kernel_launch(void* const* d_in, const int* in_sizes, int n_in,
                              void* d_out, int out_size) {
    (void)in_sizes; (void)n_in; (void)out_size;
    const float* x  = (const float*)d_in[0];
    const float* cb = (const float*)d_in[1];
    float* out = (float*)d_out;
    float* dist = out + OUT_DIST;

    k_init<<<NROW * DDIM / 256, 256>>>(x, out);
    k_cnorm<<<NQ * KCB / 8, 256>>>(cb);

    for (int q = 0; q < NQ; q++) {
        k_rownorm<<<NROW / 8, 256>>>();
        k_gemm<<<dim3(KCB / 64, NROW / 128), 256>>>(cb + (size_t)q * KCB * DDIM, dist, q);
        if (q == 0) {
            k_argmin<<<NROW / 8, 256>>>(dist);
        } else if (q == 3) {
            k_minmax<<<2048, 256>>>(dist);
            k_expQ<<<NROW / 64, 256>>>(dist);
            for (int t = 1; t <= 19; t++)
                k_iter<<<NROW / 64, 256>>>(t);
            k_fidx<<<NROW / 8, 256>>>();
        }
        k_update<<<NROW / 8, 256>>>(cb, out, q, (q == 1 || q == 2) ? 1 : 0);
    }
    k_finalize<<<1, 1>>>(out);
}

// round 4
// speedup vs baseline: 1.0016x; 1.0016x over previous
#include <cuda_runtime.h>
#include <cuda_bf16.h>
#include <math.h>
#include <stdint.h>

#define NROW 32768
#define DDIM 256
#define KCB  1024
#define NQ   4

// Output layout (concatenation of reference return tuple, all float32):
//   x_q          [NROW*DDIM]        at 0
//   mean_losses  [1]                at 8388608
//   all_indices  [NROW*NQ]          at 8388609
//   all_distances[NROW*NQ*KCB]      at 8519681   <-- ODD offset: scalar access only!
static const size_t OUT_LOSS = (size_t)NROW * DDIM;
static const size_t OUT_IDX  = OUT_LOSS + 1;
static const size_t OUT_DIST = OUT_IDX + (size_t)NROW * NQ;

// ---------------- scratch (static device globals; no allocation) ----------
__device__ __align__(16) float g_resid[(size_t)NROW * DDIM];   // 32 MB
__device__ __align__(16) float g_rn[NROW];
__device__ __align__(16) float g_cn[NQ * KCB];
__device__ __align__(16) int   g_idx[NROW];
__device__ int   g_minmax[2];
__device__ __align__(16) float g_Q0f[(size_t)NROW * KCB];      // 128 MB fp32 Q0
__device__ __align__(16) float g_SjM[21][KCB];                 // column sums per iteration
__device__ double g_loss[NQ];

// ---------------- init ---------------------------------------------------
__global__ void __launch_bounds__(256) k_init(const float* __restrict__ x,
                                              float* __restrict__ out) {
    int i = blockIdx.x * 256 + threadIdx.x;      // exactly NROW*DDIM threads
    g_resid[i] = x[i];
    out[i] = 0.0f;                               // x_q accumulator region
    if (i < NQ) g_loss[i] = 0.0;
    if (i < 21 * KCB) ((float*)g_SjM)[i] = 0.0f;
    if (i == 0) {
        g_minmax[0] = 0x7f800000;                // +inf
        g_minmax[1] = 0xff800000;                // -inf
    }
}

// ---------------- norms (warp per row) ------------------------------------
__device__ __forceinline__ float warp_sum(float s) {
#pragma unroll
    for (int o = 16; o > 0; o >>= 1) s += __shfl_xor_sync(0xffffffffu, s, o);
    return s;
}

__global__ void __launch_bounds__(256) k_cnorm(const float* __restrict__ cb) {
    int w = (blockIdx.x * blockDim.x + threadIdx.x) >> 5;  // 0..NQ*KCB-1
    int lane = threadIdx.x & 31;
    const float4* p = (const float4*)(cb + (size_t)w * DDIM);
    float4 a = p[lane], b = p[lane + 32];
    float s = a.x*a.x + a.y*a.y + a.z*a.z + a.w*a.w
            + b.x*b.x + b.y*b.y + b.z*b.z + b.w*b.w;
    s = warp_sum(s);
    if (!lane) g_cn[w] = s;
}

__global__ void __launch_bounds__(256) k_rownorm() {
    int w = (blockIdx.x * blockDim.x + threadIdx.x) >> 5;  // 0..NROW-1
    int lane = threadIdx.x & 31;
    const float4* p = (const float4*)(g_resid + (size_t)w * DDIM);
    float4 a = p[lane], b = p[lane + 32];
    float s = a.x*a.x + a.y*a.y + a.z*a.z + a.w*a.w
            + b.x*b.x + b.y*b.y + b.z*b.z + b.w*b.w;
    s = warp_sum(s);
    if (!lane) g_rn[w] = s;
}

// ---------------- distance GEMM (fp32 SIMT, 128x64 tile) ------------------
__global__ void __launch_bounds__(256) k_gemm(const float* __restrict__ B,
                                              float* __restrict__ dout, int q) {
    __shared__ float sA[16][132];   // [k][row], padded
    __shared__ float sB[16][68];    // [k][col], padded
    const int tid = threadIdx.x;
    const int bx = blockIdx.x;      // 0..15 (col tile of 64)
    const int by = blockIdx.y;      // 0..255 (row tile of 128)
    const int tx = tid & 15, ty = tid >> 4;
    const float* Ab = g_resid + (size_t)by * 128 * DDIM;
    const float* Bb = B + (size_t)bx * 64 * DDIM;

    float acc[8][4];
#pragma unroll
    for (int m = 0; m < 8; m++)
#pragma unroll
        for (int n = 0; n < 4; n++) acc[m][n] = 0.0f;

    for (int k0 = 0; k0 < DDIM; k0 += 16) {
#pragma unroll
        for (int h = 0; h < 2; h++) {
            int f = tid + h * 256;
            int r = f >> 2, cs = f & 3;
            float4 v = *(const float4*)(Ab + (size_t)r * DDIM + k0 + cs * 4);
            sA[cs*4+0][r] = v.x; sA[cs*4+1][r] = v.y;
            sA[cs*4+2][r] = v.z; sA[cs*4+3][r] = v.w;
        }
        {
            int r = tid >> 2, cs = tid & 3;
            float4 v = *(const float4*)(Bb + (size_t)r * DDIM + k0 + cs * 4);
            sB[cs*4+0][r] = v.x; sB[cs*4+1][r] = v.y;
            sB[cs*4+2][r] = v.z; sB[cs*4+3][r] = v.w;
        }
        __syncthreads();
#pragma unroll
        for (int kk = 0; kk < 16; kk++) {
            float4 a0 = *(const float4*)&sA[kk][ty * 8];
            float4 a1 = *(const float4*)&sA[kk][ty * 8 + 4];
            float4 bv = *(const float4*)&sB[kk][tx * 4];
            float av[8] = {a0.x,a0.y,a0.z,a0.w,a1.x,a1.y,a1.z,a1.w};
            float bb[4] = {bv.x,bv.y,bv.z,bv.w};
#pragma unroll
            for (int m = 0; m < 8; m++)
#pragma unroll
                for (int n = 0; n < 4; n++) acc[m][n] += av[m] * bb[n];
        }
        __syncthreads();
    }

    int colb = bx * 64 + tx * 4;
    float c0 = g_cn[q*KCB + colb + 0], c1 = g_cn[q*KCB + colb + 1];
    float c2 = g_cn[q*KCB + colb + 2], c3 = g_cn[q*KCB + colb + 3];
#pragma unroll
    for (int m = 0; m < 8; m++) {
        int row = by * 128 + ty * 8 + m;
        float rv = g_rn[row];
        // dout region is only 4-byte aligned (odd base offset) -> scalar stores
        float* o = dout + (((size_t)(row * NQ + q)) << 10) + colb;
        o[0] = rv + c0 - 2.0f * acc[m][0];
        o[1] = rv + c1 - 2.0f * acc[m][1];
        o[2] = rv + c2 - 2.0f * acc[m][2];
        o[3] = rv + c3 - 2.0f * acc[m][3];
    }
}

// ---------------- stage 0: row argmin (first-min tie-break) ----------------
__global__ void __launch_bounds__(256) k_argmin(const float* __restrict__ dout) {
    int w = (blockIdx.x * blockDim.x + threadIdx.x) >> 5;  // row
    int lane = threadIdx.x & 31;
    const float* dr = dout + (((size_t)(w * NQ)) << 10);
    float best = __int_as_float(0x7f800000);
    int bi = 0;
#pragma unroll 4
    for (int c = 0; c < 32; c++) {
        int j = c * 32 + lane;
        float v = dr[j];
        if (v < best) { best = v; bi = j; }
    }
#pragma unroll
    for (int o = 16; o > 0; o >>= 1) {
        float ov = __shfl_xor_sync(0xffffffffu, best, o);
        int   oi = __shfl_xor_sync(0xffffffffu, bi, o);
        if (ov < best || (ov == best && oi < bi)) { best = ov; bi = oi; }
    }
    if (!lane) g_idx[w] = bi;
}

// ---------------- stage 3: global min/max over d --------------------------
__global__ void __launch_bounds__(256) k_minmax(const float* __restrict__ dout) {
    size_t stride = (size_t)gridDim.x * blockDim.x;
    float mn = __int_as_float(0x7f800000), mx = -mn;
    for (size_t e = blockIdx.x * (size_t)blockDim.x + threadIdx.x;
         e < (size_t)NROW * KCB; e += stride) {
        size_t i = e >> 10, j = e & 1023;
        float v = dout[((i * NQ + 3) << 10) + j];
        mn = fminf(mn, v); mx = fmaxf(mx, v);
    }
#pragma unroll
    for (int o = 16; o > 0; o >>= 1) {
        mn = fminf(mn, __shfl_xor_sync(0xffffffffu, mn, o));
        mx = fmaxf(mx, __shfl_xor_sync(0xffffffffu, mx, o));
    }
    __shared__ float smn[8], smx[8];
    int lane = threadIdx.x & 31, wp = threadIdx.x >> 5;
    if (!lane) { smn[wp] = mn; smx[wp] = mx; }
    __syncthreads();
    if (threadIdx.x == 0) {
        for (int i = 1; i < 8; i++) { mn = fminf(mn, smn[i]); mx = fmaxf(mx, smx[i]); }
        atomicMin(&g_minmax[0], __float_as_int(mn));   // all d >= 0 -> int order ok
        atomicMax(&g_minmax[1], __float_as_int(mx));
    }
}

// ---- stage 3: Q0 = exp(-dc/eps) fp32, + unscaled colsum -> g_SjM[1] ------
// Block = 64 rows; warp per row; lane owns columns c*32+lane.
__global__ void __launch_bounds__(256) k_expQ(const float* __restrict__ dout) {
    __shared__ float sacc[KCB];
    float mn = __int_as_float(g_minmax[0]);
    float mx = __int_as_float(g_minmax[1]);
    float middle = (mx + mn) * 0.5f;
    float ampl = mx - middle + 1e-5f;
    int tid = threadIdx.x;
    for (int j = tid; j < KCB; j += 256) sacc[j] = 0.0f;
    __syncthreads();
    int wp = tid >> 5, lane = tid & 31;
    float acc[32];
#pragma unroll
    for (int c = 0; c < 32; c++) acc[c] = 0.0f;
    for (int it = 0; it < 8; it++) {
        int row = blockIdx.x * 64 + it * 8 + wp;
        const float* dr = dout + (((size_t)(row * NQ + 3)) << 10);
        float* qrow = g_Q0f + ((size_t)row << 10);
#pragma unroll
        for (int c = 0; c < 32; c++) {
            int j = c * 32 + lane;
            float dc = (dr[j] - middle) / ampl;
            float qv = expf(-dc / 0.1f);
            qrow[j] = qv;
            acc[c] += qv;
        }
    }
#pragma unroll
    for (int c = 0; c < 32; c++) atomicAdd(&sacc[c * 32 + lane], acc[c]);
    __syncthreads();
    for (int j = tid; j < KCB; j += 256) atomicAdd(&g_SjM[1][j], sacc[j]);
}

// ---- fused Sinkhorn pass t (1..19): b=1/(K*S[t]); s_i=Q0·b; a_i=1/(N*s_i);
//      S[t+1] += a_i * Q0_i.   One Q0 read per pass (row held in registers).
__global__ void __launch_bounds__(256) k_iter(int t) {
    __shared__ float sb[KCB];
    __shared__ float sacc[KCB];
    int tid = threadIdx.x;
    const float* St = g_SjM[t];
    for (int j = tid; j < KCB; j += 256) {
        sb[j] = 1.0f / (1024.0f * St[j]);
        sacc[j] = 0.0f;
    }
    __syncthreads();
    int wp = tid >> 5, lane = tid & 31;
    float acc[32];
#pragma unroll
    for (int c = 0; c < 32; c++) acc[c] = 0.0f;
    for (int it = 0; it < 8; it++) {
        int row = blockIdx.x * 64 + it * 8 + wp;
        const float* qrow = g_Q0f + ((size_t)row << 10);
        float q[32];
        float s = 0.0f;
#pragma unroll
        for (int c = 0; c < 32; c++) {
            int j = c * 32 + lane;
            q[c] = qrow[j];
            s += q[c] * sb[j];
        }
        s = warp_sum(s);
        float a = 1.0f / (32768.0f * s);
#pragma unroll
        for (int c = 0; c < 32; c++) acc[c] += a * q[c];
    }
#pragma unroll
    for (int c = 0; c < 32; c++) atomicAdd(&sacc[c * 32 + lane], acc[c]);
    __syncthreads();
    for (int j = tid; j < KCB; j += 256) atomicAdd(&g_SjM[t + 1][j], sacc[j]);
}

// ---- stage 3 final: literal argmax_j Q0_ij * b20_j (first-max tie-break) --
__global__ void __launch_bounds__(256) k_fidx() {
    __shared__ float sb[KCB];
    int tid = threadIdx.x;
    for (int j = tid; j < KCB; j += 256)
        sb[j] = 1.0f / (1024.0f * g_SjM[20][j]);
    __syncthreads();
    int wp = tid >> 5, lane = tid & 31;
    int row = blockIdx.x * 8 + wp;
    const float* qrow = g_Q0f + ((size_t)row << 10);
    float best = -1.0f;   // Q values are > 0
    int bi = 0;
#pragma unroll 4
    for (int c = 0; c < 32; c++) {
        int j = c * 32 + lane;
        float v = qrow[j] * sb[j];
        if (v > best) { best = v; bi = j; }
    }
#pragma unroll
    for (int o = 16; o > 0; o >>= 1) {
        float ov = __shfl_xor_sync(0xffffffffu, best, o);
        int   oi = __shfl_xor_sync(0xffffffffu, bi, o);
        if (ov > best || (ov == best && oi < bi)) { best = ov; bi = oi; }
    }
    if (!lane) g_idx[row] = bi;
}

// ---------------- residual/x_q update, loss, index write ------------------
__global__ void __launch_bounds__(256) k_update(const float* __restrict__ cb,
                                                float* __restrict__ out,
                                                int q, int forceZero) {
    int row = (blockIdx.x * blockDim.x + threadIdx.x) >> 5;
    int lane = threadIdx.x & 31;
    int idx = forceZero ? 0 : g_idx[row];
    const float4* c = (const float4*)(cb + ((size_t)(q * KCB + idx)) * DDIM);
    float4* r  = (float4*)(g_resid + (size_t)row * DDIM);
    float4* xq = (float4*)(out + (size_t)row * DDIM);
    float ls = 0;
#pragma unroll
    for (int h = 0; h < 2; h++) {
        int e = lane + h * 32;
        float4 cv = c[e], rv = r[e], xv = xq[e];
        float t0 = cv.x - rv.x, t1 = cv.y - rv.y, t2 = cv.z - rv.z, t3 = cv.w - rv.w;
        ls += t0*t0 + t1*t1 + t2*t2 + t3*t3;
        // x_res (value) == codeword; x_q += codeword; residual -= codeword
        xv.x += cv.x; xv.y += cv.y; xv.z += cv.z; xv.w += cv.w;
        rv.x -= cv.x; rv.y -= cv.y; rv.z -= cv.z; rv.w -= cv.w;
        r[e] = rv; xq[e] = xv;
    }
    ls = warp_sum(ls);
    if (!lane) {
        atomicAdd(&g_loss[q], (double)ls);
        out[OUT_IDX + (size_t)row * NQ + q] = (float)idx;
    }
}

__global__ void k_finalize(float* __restrict__ out) {
    double m = 0.0;
    for (int q = 0; q < NQ; q++)
        m += 1.25 * (g_loss[q] / (double)((size_t)NROW * DDIM));
    out[OUT_LOSS] = (float)(m / 4.0);
}

// ---------------- launcher ------------------------------------------------
extern "C" void kernel_launch(void* const* d_in, const int* in_sizes, int n_in,
                              void* d_out, int out_size) {
    (void)in_sizes; (void)n_in; (void)out_size;
    const float* x  = (const float*)d_in[0];
    const float* cb = (const float*)d_in[1];
    float* out = (float*)d_out;
    float* dist = out + OUT_DIST;

    k_init<<<NROW * DDIM / 256, 256>>>(x, out);
    k_cnorm<<<NQ * KCB / 8, 256>>>(cb);

    for (int q = 0; q < NQ; q++) {
        k_rownorm<<<NROW / 8, 256>>>();
        k_gemm<<<dim3(KCB / 64, NROW / 128), 256>>>(cb + (size_t)q * KCB * DDIM, dist, q);
        if (q == 0) {
            k_argmin<<<NROW / 8, 256>>>(dist);
        } else if (q == 3) {
            k_minmax<<<2048, 256>>>(dist);
            k_expQ<<<NROW / 64, 256>>>(dist);
            for (int t = 1; t <= 19; t++)
                k_iter<<<NROW / 64, 256>>>(t);
            k_fidx<<<NROW / 8, 256>>>();
        }
        k_update<<<NROW / 8, 256>>>(cb, out, q, (q == 1 || q == 2) ? 1 : 0);
    }
    k_finalize<<<1, 1>>>(out);
}

// round 9
// speedup vs baseline: 1.7871x; 1.7843x over previous
#include <cuda_runtime.h>
#include <cuda_fp16.h>
#include <math.h>
#include <stdint.h>

#define NROW 32768
#define DDIM 256
#define KCB  1024
#define NQ   4

static const size_t OUT_LOSS = (size_t)NROW * DDIM;
static const size_t OUT_IDX  = OUT_LOSS + 1;
static const size_t OUT_DIST = OUT_IDX + (size_t)NROW * NQ;  // odd: scalar access only

__device__ __align__(16) float g_resid[(size_t)NROW * DDIM];
// tiled+swizzled fp16 splits: tile = 128 rows x 64 halves (16KB), idx ((row>>7)*4 + (e>>6))
__device__ __align__(16) __half g_Ath[(size_t)NROW * DDIM];
__device__ __align__(16) __half g_Atl[(size_t)NROW * DDIM];
__device__ __align__(16) __half g_Bth[(size_t)NQ * KCB * DDIM];
__device__ __align__(16) __half g_Btl[(size_t)NQ * KCB * DDIM];
__device__ __align__(16) float g_rn[NROW];
__device__ __align__(16) float g_cn[NQ * KCB];
__device__ __align__(16) unsigned long long g_best[NROW];
__device__ __align__(16) int   g_idx[NROW];
__device__ int    g_minmax[2];
__device__ __align__(16) float g_Q0f[(size_t)NROW * KCB];
__device__ __align__(16) float g_SjM[21][KCB];
__device__ double g_loss[NQ];

__device__ __forceinline__ uint32_t smem_u32(const void* p) {
    uint32_t a;
    asm("{ .reg .u64 t; cvta.to.shared.u64 t, %1; cvt.u32.u64 %0, t; }" : "=r"(a) : "l"(p));
    return a;
}
#define MBAR_INIT(a, c) asm volatile("mbarrier.init.shared.b64 [%0], %1;" :: "r"(a), "r"(c) : "memory")
#define MBAR_EXPTX(a, n) asm volatile("mbarrier.arrive.expect_tx.shared.b64 _, [%0], %1;" :: "r"(a), "r"(n) : "memory")
#define MBAR_WAIT(a, p) do { uint32_t _m = (a), _p = (p), _d;                    \
    asm volatile("{\n.reg .pred p;\n"                                           \
        "mbarrier.try_wait.parity.acquire.cta.shared::cta.b64 p, [%1], %2;\n"   \
        "selp.b32 %0, 1, 0, p;\n}" : "=r"(_d) : "r"(_m), "r"(_p) : "memory");   \
    if (!_d) { asm volatile("{\n.reg .pred P1;\nWL_%=:\n"                       \
        "mbarrier.try_wait.parity.acquire.cta.shared::cta.b64 P1, [%0], %1, 0x989680;\n" \
        "@P1 bra.uni WD_%=;\nbra.uni WL_%=;\nWD_%=:\n}"                         \
        :: "r"(_m), "r"(_p) : "memory"); } } while (0)
#define BULK(sa, g, n, mb) asm volatile( \
    "cp.async.bulk.shared::cluster.global.mbarrier::complete_tx::bytes [%0], [%1], %2, [%3];" \
    :: "r"(sa), "l"(g), "r"(n), "r"(mb) : "memory")
#define SWZ128(o) ((o) ^ (((o) >> 3) & 0x70))
#define LDSM4(r, a) asm volatile("ldmatrix.sync.aligned.m8n8.x4.shared.b16 {%0,%1,%2,%3}, [%4];" \
    : "=r"((r)[0]), "=r"((r)[1]), "=r"((r)[2]), "=r"((r)[3]) : "r"(a))
#define LDSM2(r0, r1, a) asm volatile("ldmatrix.sync.aligned.m8n8.x2.shared.b16 {%0,%1}, [%2];" \
    : "=r"(r0), "=r"(r1) : "r"(a))
#define MMA(c, a, b0, b1) asm volatile( \
    "mma.sync.aligned.m16n8k16.row.col.f32.f16.f16.f32 {%0,%1,%2,%3}, {%4,%5,%6,%7}, {%8,%9}, {%0,%1,%2,%3};" \
    : "+f"((c)[0]), "+f"((c)[1]), "+f"((c)[2]), "+f"((c)[3]) \
    : "r"((a)[0]), "r"((a)[1]), "r"((a)[2]), "r"((a)[3]), "r"(b0), "r"(b1))

__device__ __forceinline__ float warp_sum(float s) {
#pragma unroll
    for (int o = 16; o > 0; o >>= 1) s += __shfl_xor_sync(0xffffffffu, s, o);
    return s;
}
__device__ __forceinline__ void wsplitT(__half* H, __half* L, int row, int e, float4 v) {
    size_t base = ((size_t)((row >> 7) * 4 + (e >> 6))) << 13;
    uint32_t off = SWZ128((uint32_t)(row & 127) * 128 + (e & 63) * 2) >> 1;
    __half h0 = __float2half_rn(v.x), h1 = __float2half_rn(v.y);
    __half h2 = __float2half_rn(v.z), h3 = __float2half_rn(v.w);
    __half l0 = __float2half_rn(v.x - __half2float(h0));
    __half l1 = __float2half_rn(v.y - __half2float(h1));
    __half l2 = __float2half_rn(v.z - __half2float(h2));
    __half l3 = __float2half_rn(v.w - __half2float(h3));
    __half2* ph = (__half2*)(H + base + off);
    ph[0] = __halves2half2(h0, h1); ph[1] = __halves2half2(h2, h3);
    __half2* pl = (__half2*)(L + base + off);
    pl[0] = __halves2half2(l0, l1); pl[1] = __halves2half2(l2, l3);
}

__global__ void __launch_bounds__(256) k_init(const float* __restrict__ x,
                                              float* __restrict__ out) {
    int tid = threadIdx.x, wp = tid >> 5, lane = tid & 31;
    size_t f = (size_t)blockIdx.x * 256 + tid;
    if (f < 21 * KCB) ((float*)g_SjM)[f] = 0.0f;
    if (f < NQ) g_loss[f] = 0.0;
    if (f == 0) { g_minmax[0] = 0x7f800000; g_minmax[1] = 0xff800000; }
    int row = blockIdx.x * 8 + wp;
    const float4* xr = (const float4*)(x + (size_t)row * DDIM);
    float4* rr  = (float4*)(g_resid + (size_t)row * DDIM);
    float4* xqr = (float4*)(out + (size_t)row * DDIM);
    float s = 0.0f; float4 z = {0, 0, 0, 0};
#pragma unroll
    for (int h = 0; h < 2; h++) {
        int e = lane + 32 * h;
        float4 v = xr[e];
        rr[e] = v; xqr[e] = z;
        s += v.x*v.x + v.y*v.y + v.z*v.z + v.w*v.w;
        wsplitT(g_Ath, g_Atl, row, e * 4, v);
    }
    s = warp_sum(s);
    if (!lane) { g_rn[row] = s; g_best[row] = 0x7F80000000000000ull; }
}

__global__ void __launch_bounds__(256) k_bprep(const float* __restrict__ cb) {
    int tid = threadIdx.x, wp = tid >> 5, lane = tid & 31;
    int row = blockIdx.x * 8 + wp;
    const float4* p = (const float4*)(cb + (size_t)row * DDIM);
    float s = 0.0f;
#pragma unroll
    for (int h = 0; h < 2; h++) {
        int e = lane + 32 * h;
        float4 v = p[e];
        s += v.x*v.x + v.y*v.y + v.z*v.z + v.w*v.w;
        wsplitT(g_Bth, g_Btl, row, e * 4, v);
    }
    s = warp_sum(s);
    if (!lane) g_cn[row] = s;
}

#define SM_TOT 66576

__global__ void __launch_bounds__(256) k_gemm_tc(float* __restrict__ dout, int q) {
    extern __shared__ char sm[];
    uint32_t smb = smem_u32(sm);
    int tid = threadIdx.x, wid = tid >> 5, lane = tid & 31;
    int bx = blockIdx.x, by = blockIdx.y;
    uint32_t mb0 = smb + 66560, mb1 = mb0 + 8;
    if (tid == 0) { MBAR_INIT(mb0, 1); MBAR_INIT(mb1, 1); }
    __syncthreads();

    const __half* As[2] = {g_Ath, g_Atl};
    const __half* Bs[2] = {g_Bth, g_Btl};
    const int SA3[3] = {0, 0, 1}, SB3[3] = {0, 1, 0};
    float c[2][8][4];
#pragma unroll
    for (int m = 0; m < 2; m++)
#pragma unroll
        for (int n = 0; n < 8; n++)
#pragma unroll
            for (int i = 0; i < 4; i++) c[m][n][i] = 0.0f;

    int wm = wid >> 1, wn = wid & 1;
    uint32_t aOff = (uint32_t)(wm * 32 + (lane & 15)) * 128 + ((lane >> 4) & 1) * 16;
    uint32_t bOff = (uint32_t)(wn * 64 + (lane & 7)) * 128 + ((lane >> 3) & 1) * 16;

    if (tid == 0) {
        MBAR_EXPTX(mb0, 32768);
        BULK(smb, As[0] + ((size_t)(by * 4) << 13), 16384, mb0);
        BULK(smb + 32768, Bs[0] + ((size_t)((q * 8 + bx) * 4) << 13), 16384, mb0);
    }
    for (int seg = 0; seg < 12; seg++) {
        if (tid == 0 && seg + 1 < 12) {
            int p = (seg + 1) >> 2, ch = (seg + 1) & 3, b = (seg + 1) & 1;
            uint32_t mb = b ? mb1 : mb0;
            MBAR_EXPTX(mb, 32768);
            BULK(smb + b * 16384, As[SA3[p]] + ((size_t)(by * 4 + ch) << 13), 16384, mb);
            BULK(smb + 32768 + b * 16384,
                 Bs[SB3[p]] + ((size_t)((q * 8 + bx) * 4 + ch) << 13), 16384, mb);
        }
        int b = seg & 1;
        MBAR_WAIT(b ? mb1 : mb0, (seg >> 1) & 1);
        uint32_t sA = smb + b * 16384, sB = smb + 32768 + b * 16384;
#pragma unroll
        for (int k = 0; k < 4; k++) {
            uint32_t a0[4], a1[4];
            LDSM4(a0, sA + SWZ128(aOff + k * 32));
            LDSM4(a1, sA + SWZ128(aOff + 2048 + k * 32));
#pragma unroll
            for (int nt = 0; nt < 8; nt++) {
                uint32_t b0, b1;
                LDSM2(b0, b1, sB + SWZ128(bOff + nt * 1024 + k * 32));
                MMA(c[0][nt], a0, b0, b1);
                MMA(c[1][nt], a1, b0, b1);
            }
        }
        __syncthreads();
    }

    // epilogue: correct C fragment map: i>>1 -> +8 rows, i&1 -> +1 col
    float* stg = (float*)sm + wid * (32 * 65);
#pragma unroll
    for (int mt = 0; mt < 2; mt++)
#pragma unroll
        for (int nt = 0; nt < 8; nt++)
#pragma unroll
            for (int i = 0; i < 4; i++) {
                int rr = mt * 16 + (lane >> 2) + (i >> 1) * 8;
                int cc = nt * 8 + (lane & 3) * 2 + (i & 1);
                int grow = by * 128 + wm * 32 + rr;
                int gcol = bx * 128 + wn * 64 + cc;
                stg[rr * 65 + cc] = g_rn[grow] + g_cn[q * KCB + gcol] - 2.0f * c[mt][nt][i];
            }
    __syncwarp();
#pragma unroll 2
    for (int rr = 0; rr < 32; rr++) {
        size_t grow = (size_t)by * 128 + wm * 32 + rr;
        float* o = dout + ((grow * 4 + q) << 10) + bx * 128 + wn * 64;
        o[lane] = stg[rr * 65 + lane];
        o[32 + lane] = stg[rr * 65 + 32 + lane];
    }
    if (q == 0) {
        size_t grow = (size_t)by * 128 + wm * 32 + lane;
        float bestv = __int_as_float(0x7f800000); int besti = 0;
#pragma unroll 8
        for (int cc = 0; cc < 64; cc++) {
            float v = stg[lane * 65 + cc];
            if (v < bestv) { bestv = v; besti = bx * 128 + wn * 64 + cc; }
        }
        unsigned long long pk = ((unsigned long long)__float_as_uint(bestv) << 32) | (unsigned)besti;
        atomicMin(&g_best[grow], pk);
    } else if (q == 3) {
        float mn = __int_as_float(0x7f800000), mx = -mn;
#pragma unroll 8
        for (int cc = 0; cc < 64; cc++) {
            float v = stg[lane * 65 + cc];
            mn = fminf(mn, v); mx = fmaxf(mx, v);
        }
#pragma unroll
        for (int o = 16; o > 0; o >>= 1) {
            mn = fminf(mn, __shfl_xor_sync(0xffffffffu, mn, o));
            mx = fmaxf(mx, __shfl_xor_sync(0xffffffffu, mx, o));
        }
        if (!lane) {
            atomicMin(&g_minmax[0], __float_as_int(mn));
            atomicMax(&g_minmax[1], __float_as_int(mx));
        }
    }
}

__global__ void __launch_bounds__(256) k_expQ(const float* __restrict__ dout) {
    __shared__ float sacc[KCB];
    float mn = __int_as_float(g_minmax[0]);
    float mx = __int_as_float(g_minmax[1]);
    float middle = (mx + mn) * 0.5f;
    float inv = 10.0f / (mx - middle + 1e-5f);
    int tid = threadIdx.x;
    for (int j = tid; j < KCB; j += 256) sacc[j] = 0.0f;
    __syncthreads();
    int wp = tid >> 5, lane = tid & 31;
    float acc[32];
#pragma unroll
    for (int cc = 0; cc < 32; cc++) acc[cc] = 0.0f;
    for (int it = 0; it < 8; it++) {
        int row = blockIdx.x * 64 + it * 8 + wp;
        const float* dr = dout + (((size_t)(row * NQ + 3)) << 10);
        float* qrow = g_Q0f + ((size_t)row << 10);
#pragma unroll
        for (int cc = 0; cc < 32; cc++) {
            int j = cc * 32 + lane;
            float qv = expf(-(dr[j] - middle) * inv);
            qrow[j] = qv;
            acc[cc] += qv;
        }
    }
#pragma unroll
    for (int cc = 0; cc < 32; cc++) atomicAdd(&sacc[cc * 32 + lane], acc[cc]);
    __syncthreads();
    for (int j = tid; j < KCB; j += 256) atomicAdd(&g_SjM[1][j], sacc[j]);
}

__global__ void __launch_bounds__(256) k_iter(int t) {
    __shared__ float4 sb4[256];
    __shared__ float sacc[KCB];
    int tid = threadIdx.x;
    {
        float4 s = ((const float4*)g_SjM[t])[tid];
        float4 b;
        b.x = 1.0f/(1024.0f*s.x); b.y = 1.0f/(1024.0f*s.y);
        b.z = 1.0f/(1024.0f*s.z); b.w = 1.0f/(1024.0f*s.w);
        sb4[tid] = b;
#pragma unroll
        for (int u = 0; u < 4; u++) sacc[tid + u * 256] = 0.0f;
    }
    __syncthreads();
    int wp = tid >> 5, lane = tid & 31;
    float4 acc[8];
#pragma unroll
    for (int cc = 0; cc < 8; cc++) acc[cc] = make_float4(0, 0, 0, 0);
    for (int it = 0; it < 8; it++) {
        int row = blockIdx.x * 64 + it * 8 + wp;
        const float4* qr = (const float4*)(g_Q0f + ((size_t)row << 10));
        float s = 0.0f;
        float4 qv[8];
#pragma unroll
        for (int cc = 0; cc < 8; cc++) {
            qv[cc] = qr[cc * 32 + lane];
            float4 b = sb4[cc * 32 + lane];
            s += qv[cc].x*b.x + qv[cc].y*b.y + qv[cc].z*b.z + qv[cc].w*b.w;
        }
        s = warp_sum(s);
        float a = 1.0f / (32768.0f * s);
#pragma unroll
        for (int cc = 0; cc < 8; cc++) {
            acc[cc].x += a*qv[cc].x; acc[cc].y += a*qv[cc].y;
            acc[cc].z += a*qv[cc].z; acc[cc].w += a*qv[cc].w;
        }
    }
#pragma unroll
    for (int cc = 0; cc < 8; cc++) {
        int j = (cc * 32 + lane) * 4;
        atomicAdd(&sacc[j+0], acc[cc].x); atomicAdd(&sacc[j+1], acc[cc].y);
        atomicAdd(&sacc[j+2], acc[cc].z); atomicAdd(&sacc[j+3], acc[cc].w);
    }
    __syncthreads();
#pragma unroll
    for (int u = 0; u < 4; u++)
        atomicAdd(&g_SjM[t + 1][tid + u * 256], sacc[tid + u * 256]);
}

__global__ void __launch_bounds__(256) k_fidx() {
    __shared__ float sb[KCB];
    int tid = threadIdx.x;
    for (int j = tid; j < KCB; j += 256)
        sb[j] = 1.0f / (1024.0f * g_SjM[20][j]);
    __syncthreads();
    int wp = tid >> 5, lane = tid & 31;
    int row = blockIdx.x * 8 + wp;
    const float* qrow = g_Q0f + ((size_t)row << 10);
    float best = -1.0f;
    int bi = 0;
#pragma unroll 4
    for (int cc = 0; cc < 32; cc++) {
        int j = cc * 32 + lane;
        float v = qrow[j] * sb[j];
        if (v > best) { best = v; bi = j; }
    }
#pragma unroll
    for (int o = 16; o > 0; o >>= 1) {
        float ov = __shfl_xor_sync(0xffffffffu, best, o);
        int   oi = __shfl_xor_sync(0xffffffffu, bi, o);
        if (ov > best || (ov == best && oi < bi)) { best = ov; bi = oi; }
    }
    if (!lane) g_idx[row] = bi;
}

__global__ void __launch_bounds__(256) k_update(const float* __restrict__ cb,
                                                float* __restrict__ out, int q) {
    int row = (blockIdx.x * blockDim.x + threadIdx.x) >> 5;
    int lane = threadIdx.x & 31;
    int idx;
    if (q == 0) idx = (int)(unsigned)(g_best[row] & 0xffffffffull);
    else if (q == 3) idx = g_idx[row];
    else idx = 0;  // stages 1,2: reference sinkhorn overflows -> all-NaN -> argmax 0
    const float4* c = (const float4*)(cb + ((size_t)(q * KCB + idx)) * DDIM);
    float4* r  = (float4*)(g_resid + (size_t)row * DDIM);
    float4* xq = (float4*)(out + (size_t)row * DDIM);
    float ls = 0, s = 0;
#pragma unroll
    for (int h = 0; h < 2; h++) {
        int e = lane + h * 32;
        float4 cv = c[e], rv = r[e], xv = xq[e];
        float t0 = cv.x-rv.x, t1 = cv.y-rv.y, t2 = cv.z-rv.z, t3 = cv.w-rv.w;
        ls += t0*t0 + t1*t1 + t2*t2 + t3*t3;
        xv.x += cv.x; xv.y += cv.y; xv.z += cv.z; xv.w += cv.w;
        rv.x -= cv.x; rv.y -= cv.y; rv.z -= cv.z; rv.w -= cv.w;
        r[e] = rv; xq[e] = xv;
        if (q < 3) {
            s += rv.x*rv.x + rv.y*rv.y + rv.z*rv.z + rv.w*rv.w;
            wsplitT(g_Ath, g_Atl, row, e * 4, rv);
        }
    }
    if (q < 3) {
        s = warp_sum(s);
        if (!lane) g_rn[row] = s;
    }
    ls = warp_sum(ls);
    if (!lane) {
        atomicAdd(&g_loss[q], (double)ls);
        out[OUT_IDX + (size_t)row * NQ + q] = (float)idx;
    }
}

__global__ void k_finalize(float* __restrict__ out) {
    double m = 0.0;
    for (int q = 0; q < NQ; q++)
        m += 1.25 * (g_loss[q] / (double)((size_t)NROW * DDIM));
    out[OUT_LOSS] = (float)(m / 4.0);
}

extern "C" void kernel_launch(void* const* d_in, const int* in_sizes, int n_in,
                              void* d_out, int out_size) {
    (void)in_sizes; (void)n_in; (void)out_size;
    const float* x  = (const float*)d_in[0];
    const float* cb = (const float*)d_in[1];
    float* out = (float*)d_out;
    float* dist = out + OUT_DIST;

    cudaFuncSetAttribute(k_gemm_tc, cudaFuncAttributeMaxDynamicSharedMemorySize, SM_TOT);

    k_init<<<NROW / 8, 256>>>(x, out);
    k_bprep<<<NQ * KCB / 8, 256>>>(cb);

    for (int q = 0; q < NQ; q++) {
        k_gemm_tc<<<dim3(8, NROW / 128), 256, SM_TOT>>>(dist, q);
        if (q == 3) {
            k_expQ<<<NROW / 64, 256>>>(dist);
            for (int t = 1; t <= 19; t++)
                k_iter<<<NROW / 64, 256>>>(t);
            k_fidx<<<NROW / 8, 256>>>();
        }
        k_update<<<NROW / 8, 256>>>(cb, out, q);
    }
    k_finalize<<<1, 1>>>(out);
}